// round 14
// baseline (speedup 1.0000x reference)
#include <cuda_runtime.h>

// ---------------- NAVAR dims ----------------
#define ND      2
#define NS      4
#define NV      12
#define HID     16
#define GROUPS  96
#define KS      4
#define T       2048
#define BATCH   8

// ---------------- tiling ----------------
#define TT      420              // output timesteps per tile
#define HALO    28               // 3 + 3*(1+2+4)
#define LL      (TT + HALO)      // 448 local positions = 14 * 32
#define NJ      14               // j-vectors of 32
#define PITCH   452              // row pitch (floats); 452*4 B is 16B-divisible
#define NTHREADS 256
#define NTILES  5                // 5*420 = 2100 >= 2048
#define PRED_ELEMS (BATCH*ND*NS*NV*T)        // 1,572,864
#define GUARD   16               // floats of scratch before bufA (negative-j reads)

typedef unsigned long long u64;

// ---- packed f32x2 helpers (Blackwell) ----
__device__ __forceinline__ u64 pk2(float a, float b) {
    u64 r; asm("mov.b64 %0, {%1, %2};" : "=l"(r) : "f"(a), "f"(b)); return r;
}
__device__ __forceinline__ u64 dup2f(float a) {
    u64 r; asm("mov.b64 %0, {%1, %1};" : "=l"(r) : "f"(a)); return r;
}
__device__ __forceinline__ void fma2(u64 &d, u64 a, u64 b) {
    asm("fma.rn.f32x2 %0, %1, %2, %0;" : "+l"(d) : "l"(a), "l"(b));
}
__device__ __forceinline__ void unpk(u64 v, float &lo, float &hi) {
    asm("mov.b64 {%0, %1}, %2;" : "=f"(lo), "=f"(hi) : "l"(v));
}
__device__ __forceinline__ void red_add_f32(float* p, float v) {
    asm volatile("red.global.add.f32 [%0], %1;" :: "l"(p), "f"(v) : "memory");
}

struct __align__(16) Smem {
    float bufs[GUARD + 2 * HID * PITCH]; // bufA, bufB back-to-back   57,920 B
    float xsb[4 + PITCH];                //                             1,824 B
    u64   whp[3][HID * 8 * KS];          // all 3 layers co-paired     12,288 B
    u64   woutp[HID * 6];                //                               768 B
    u64   boutp[6];                      //                                48 B
    float w_in[HID * KS];                //                               256 B
    float b_in[HID];                     //                                64 B
    float b_h[3 * HID];                  //                               192 B
};  // ~73.4 KB dynamic; x3 CTAs = ~220 KB/SM

// ---- hidden conv HID->HID dilation D, co-paired, 3-4 j-vectors/warp ----
// warp: cg = wid>>2 -> co 8*cg..8*cg+7 (4 packed pairs);
//       q  = wid&3  -> j-vectors {q + 4r : q + 4r < NJ}  (q<2 -> 4, else 3).
template<int D, int S>
__device__ __forceinline__ void hidden_cp4(
    const float* __restrict__ in, float* __restrict__ out,
    const u64* __restrict__ wp, const float* __restrict__ bl,
    int gt0, int lane, int wid)
{
    const int cg = wid >> 2;
    const int q  = wid & 3;
    const int nr = (q < 2) ? 4 : 3;      // q+4r < NJ=14

    u64 acc[4][4];
    #pragma unroll
    for (int p = 0; p < 4; p++) {
        u64 bp = pk2(bl[cg * 8 + 2 * p], bl[cg * 8 + 2 * p + 1]);
        #pragma unroll
        for (int r = 0; r < 4; r++) acc[p][r] = bp;
    }

    #pragma unroll 1
    for (int ci = 0; ci < HID; ci++) {
        const float* row = in + ci * PITCH;
        u64 vd[4][4];
        #pragma unroll
        for (int r = 0; r < 4; r++) {
            if (r < nr) {
                const int j = (q + 4 * r) * 32 + lane;
                vd[r][0] = dup2f(row[j - 3 * D]);
                vd[r][1] = dup2f(row[j - 2 * D]);
                vd[r][2] = dup2f(row[j - 1 * D]);
                vd[r][3] = dup2f(row[j]);
            }
        }
        const ulonglong2* w2 = (const ulonglong2*)(wp + ci * 32 + cg * 16);
        #pragma unroll
        for (int p = 0; p < 4; p++) {
            ulonglong2 wa = w2[2 * p], wb = w2[2 * p + 1];
            #pragma unroll
            for (int r = 0; r < 4; r++) {
                if (r < nr) {
                    fma2(acc[p][r], wa.x, vd[r][0]);
                    fma2(acc[p][r], wa.y, vd[r][1]);
                    fma2(acc[p][r], wb.x, vd[r][2]);
                    fma2(acc[p][r], wb.y, vd[r][3]);
                }
            }
        }
    }

    #pragma unroll
    for (int p = 0; p < 4; p++) {
        const int co0 = cg * 8 + 2 * p;
        #pragma unroll
        for (int r = 0; r < 4; r++) {
            if (r < nr) {
                const int j = (q + 4 * r) * 32 + lane;
                if (j >= S) {
                    float a0, a1; unpk(acc[p][r], a0, a1);
                    bool z = (gt0 + j) < 0;
                    out[co0 * PITCH + j]       = z ? 0.f : fmaxf(a0, 0.f);
                    out[(co0 + 1) * PITCH + j] = z ? 0.f : fmaxf(a1, 0.f);
                }
            }
        }
    }
}

__global__ void __launch_bounds__(NTHREADS, 3)
navar_main_kernel(const float* __restrict__ x,
                  const float* __restrict__ w_in, const float* __restrict__ b_in,
                  const float* __restrict__ w_h,  const float* __restrict__ b_h,
                  const float* __restrict__ w_out,const float* __restrict__ b_out,
                  float* __restrict__ out_contrib,
                  float* __restrict__ out_pred)
{
    extern __shared__ __align__(16) char smraw[];
    Smem& s = *reinterpret_cast<Smem*>(smraw);
    float* bufA = s.bufs + GUARD;
    float* bufB = bufA + HID * PITCH;
    float* xs   = s.xsb + 4;

    const int tile = blockIdx.x;
    const int g    = blockIdx.y;
    const int b    = blockIdx.z;
    const int t0   = tile * TT;
    const int gt0  = t0 - HALO;
    const int tid  = threadIdx.x;
    const int lane = tid & 31;
    const int wid  = tid >> 5;

    // ---- stage x tile + all params (all 3 hidden layers prestaged) ----
    const float* xg = x + ((size_t)b * GROUPS + g) * T;
    for (int j = tid; j < PITCH; j += NTHREADS) {
        int gt = gt0 + j;
        xs[j] = (gt >= 0 && gt < T) ? xg[gt] : 0.f;
    }
    if (tid < HID * KS) s.w_in[tid] = w_in[g * HID * KS + tid];
    if (tid < HID)      s.b_in[tid] = b_in[g * HID + tid];
    for (int i = tid; i < 3 * HID; i += NTHREADS) {
        int L = i >> 4, co = i & 15;
        s.b_h[i] = b_h[L * GROUPS * HID + g * HID + co];
    }
    for (int i = tid; i < HID * 6 * 2; i += NTHREADS) {
        int half = i & 1, dp = (i >> 1) % 6, ci = (i >> 1) / 6;
        ((float*)s.woutp)[i] = w_out[((size_t)g * NV + 2 * dp + half) * HID + ci];
    }
    if (tid < 12) {
        int half = tid & 1, dp = tid >> 1;
        ((float*)s.boutp)[tid] = b_out[g * NV + 2 * dp + half];
    }
    // hidden weights, co-paired: whp[L][(ci*8+pg)*4+k] = (w[2pg][ci][k], w[2pg+1][ci][k])
    #pragma unroll 1
    for (int L = 0; L < 3; L++) {
        const float* wsrc = w_h + ((size_t)L * GROUPS * HID + (size_t)g * HID) * (HID * KS);
        float* wdst = (float*)s.whp[L];
        #pragma unroll
        for (int r = 0; r < 4; r++) {
            int i = tid + r * NTHREADS;       // 0..1023
            int half = i & 1, k = (i >> 1) & 3, pg = (i >> 3) & 7, ci = i >> 6;
            wdst[i] = wsrc[((2 * pg + half) * HID + ci) * KS + k];
        }
    }
    __syncthreads();

    // ---- input conv 1 -> HID (thread = timestep j) -> bufA ----
    for (int j = tid; j < LL; j += NTHREADS) {
        float xv0 = xs[j - 3], xv1 = xs[j - 2], xv2 = xs[j - 1], xv3 = xs[j];
        const bool neg = (gt0 + j) < 0;
        #pragma unroll
        for (int co = 0; co < HID; co++) {
            float4 w = *(const float4*)(s.w_in + co * 4);
            float a = s.b_in[co];
            a = fmaf(w.x, xv0, a); a = fmaf(w.y, xv1, a);
            a = fmaf(w.z, xv2, a); a = fmaf(w.w, xv3, a);
            bufA[co * PITCH + j] = neg ? 0.f : fmaxf(a, 0.f);
        }
    }
    __syncthreads();

    hidden_cp4<1,  8>(bufA, bufB, s.whp[0], s.b_h,           gt0, lane, wid);
    __syncthreads();
    hidden_cp4<2, 16>(bufB, bufA, s.whp[1], s.b_h + HID,     gt0, lane, wid);
    __syncthreads();
    hidden_cp4<4, 28>(bufA, bufB, s.whp[2], s.b_h + 2 * HID, gt0, lane, wid);
    __syncthreads();

    // ---- 1x1 output conv: thread = timestep, 12 dst as 6 packed pairs.
    // Writes contributions AND accumulates prediction via global reductions
    // (pred pre-initialized with biases by navar_init_kernel).
    {
        const int dd  = g / (NS * NV);
        const int rem = g % (NS * NV);
        const int ss  = rem / NV;
        const int src = rem % NV;
        const size_t cbase = ((size_t)((b * ND + dd) * NS + ss) * NV * NV + src) * T;
        float* pbase = out_pred + ((size_t)((b * ND + dd) * NS + ss)) * NV * T;

        for (int trel = tid; trel < TT; trel += NTHREADS) {
            const int gt = t0 + trel;
            if (gt >= T) break;
            const int jc = HALO + trel;

            u64 a6[6];
            #pragma unroll
            for (int dp = 0; dp < 6; dp++) a6[dp] = s.boutp[dp];

            #pragma unroll
            for (int ci = 0; ci < HID; ci++) {
                u64 hd = dup2f(bufB[ci * PITCH + jc]);
                const ulonglong2* w2 = (const ulonglong2*)(s.woutp + ci * 6);
                ulonglong2 wA = w2[0], wB = w2[1], wC = w2[2];
                fma2(a6[0], wA.x, hd); fma2(a6[1], wA.y, hd);
                fma2(a6[2], wB.x, hd); fma2(a6[3], wB.y, hd);
                fma2(a6[4], wC.x, hd); fma2(a6[5], wC.y, hd);
            }
            #pragma unroll
            for (int dp = 0; dp < 6; dp++) {
                float lo, hi; unpk(a6[dp], lo, hi);
                out_contrib[cbase + (size_t)(2 * dp)     * NV * T + gt] = lo;
                out_contrib[cbase + (size_t)(2 * dp + 1) * NV * T + gt] = hi;
                red_add_f32(pbase + (size_t)(2 * dp)     * T + gt, lo);
                red_add_f32(pbase + (size_t)(2 * dp + 1) * T + gt, hi);
            }
        }
    }
}

// pred[b,dd,ss,v,t] = biases[dd,ss,v]  (main kernel REDs contributions on top)
__global__ void __launch_bounds__(256)
navar_init_kernel(const float* __restrict__ biases, float4* __restrict__ pred4)
{
    int idx = blockIdx.x * blockDim.x + threadIdx.x;
    if (idx >= PRED_ELEMS / 4) return;
    int r = idx >> 9;                  // T/4 = 512
    float bsc = biases[r % (ND * NS * NV)];
    pred4[idx] = make_float4(bsc, bsc, bsc, bsc);
}

extern "C" void kernel_launch(void* const* d_in, const int* in_sizes, int n_in,
                              void* d_out, int out_size)
{
    const float* x      = (const float*)d_in[0];
    const float* w_in   = (const float*)d_in[1];
    const float* b_in   = (const float*)d_in[2];
    const float* w_h    = (const float*)d_in[3];
    const float* b_h    = (const float*)d_in[4];
    const float* w_out  = (const float*)d_in[5];
    const float* b_out  = (const float*)d_in[6];
    const float* biases = (const float*)d_in[7];

    float* out     = (float*)d_out;
    float* pred    = out;                     // (B,ND,NS,NV,T)
    float* contrib = out + PRED_ELEMS;        // (B,ND,NS,NV,NV,T)

    const int smem_bytes = (int)sizeof(Smem);
    cudaFuncSetAttribute(navar_main_kernel,
                         cudaFuncAttributeMaxDynamicSharedMemorySize, smem_bytes);

    navar_init_kernel<<<(PRED_ELEMS / 4 + 255) / 256, 256>>>(biases, (float4*)pred);

    dim3 grid(NTILES, GROUPS, BATCH);
    navar_main_kernel<<<grid, NTHREADS, smem_bytes>>>(
        x, w_in, b_in, w_h, b_h, w_out, b_out, contrib, pred);
}

// round 16
// speedup vs baseline: 1.0014x; 1.0014x over previous
#include <cuda_runtime.h>

// ---------------- NAVAR dims ----------------
#define ND      2
#define NS      4
#define NV      12
#define HID     16
#define GROUPS  96
#define KS      4
#define T       2048
#define BATCH   8

// ---------------- tiling ----------------
#define TT      420              // output timesteps per tile (even)
#define HALO    28               // 3 + 3*(1+2+4)
#define LL      (TT + HALO)      // 448 local positions = 14 * 32
#define NJ      14               // j-vectors of 32
#define PITCH   452              // row pitch (floats); 452*4 B is 16B-divisible
#define NTHREADS 256
#define NTILES  5                // 5*420 = 2100 >= 2048
#define PRED_ELEMS (BATCH*ND*NS*NV*T)        // 1,572,864
#define GUARD   16               // floats of scratch before bufA (negative-j reads)

typedef unsigned long long u64;

// ---- packed f32x2 helpers (Blackwell) ----
__device__ __forceinline__ u64 pk2(float a, float b) {
    u64 r; asm("mov.b64 %0, {%1, %2};" : "=l"(r) : "f"(a), "f"(b)); return r;
}
__device__ __forceinline__ u64 dup2f(float a) {
    u64 r; asm("mov.b64 %0, {%1, %1};" : "=l"(r) : "f"(a)); return r;
}
__device__ __forceinline__ void fma2(u64 &d, u64 a, u64 b) {
    asm("fma.rn.f32x2 %0, %1, %2, %0;" : "+l"(d) : "l"(a), "l"(b));
}
__device__ __forceinline__ void unpk(u64 v, float &lo, float &hi) {
    asm("mov.b64 {%0, %1}, %2;" : "=f"(lo), "=f"(hi) : "l"(v));
}
// forced 64-bit shared load (prevents LDS.128 coalescing)
__device__ __forceinline__ u64 lds64(unsigned saddr) {
    u64 r; asm("ld.shared.b64 %0, [%1];" : "=l"(r) : "r"(saddr)); return r;
}

struct __align__(16) Smem {
    float bufs[GUARD + 2 * HID * PITCH]; // bufA, bufB back-to-back   57,920 B
    float xsb[4 + PITCH];                //                             1,824 B
    u64   whp[3][HID * 8 * KS];          // all 3 layers co-paired     12,288 B
    u64   woutp[HID * 6];                //                               768 B
    u64   boutp[6];                      //                                48 B
    float w_in[HID * KS];                //                               256 B
    float b_in[HID];                     //                                64 B
    float b_h[3 * HID];                  //                               192 B
};  // ~73.4 KB dynamic; x3 CTAs = ~220 KB/SM

// ---- hidden conv HID->HID dilation D, co-paired, SMSP-balanced jvec sets ----
// warp: cg = wid>>2 -> co 8*cg..8*cg+7 (4 packed pairs);
//       logical jb: cg0 uses q, cg1 uses (q+2)&3 -> every SMSP gets 4+3 jvecs.
//       jvecs {jb + 4r : jb + 4r < NJ}  (jb<2 -> 4, else 3).
// Weights loaded per co-pair as 4x LDS.64 broadcasts (width-proportional cost).
template<int D, int S>
__device__ __forceinline__ void hidden_cp4(
    const float* __restrict__ in, float* __restrict__ out,
    const u64* __restrict__ wp, const float* __restrict__ bl,
    int gt0, int lane, int wid)
{
    const int cg = wid >> 2;
    const int q  = wid & 3;
    const int jb = cg ? ((q + 2) & 3) : q;
    const int nr = (jb < 2) ? 4 : 3;      // jb+4r < NJ=14

    u64 acc[4][4];
    #pragma unroll
    for (int p = 0; p < 4; p++) {
        u64 bp = pk2(bl[cg * 8 + 2 * p], bl[cg * 8 + 2 * p + 1]);
        #pragma unroll
        for (int r = 0; r < 4; r++) acc[p][r] = bp;
    }

    #pragma unroll 1
    for (int ci = 0; ci < HID; ci++) {
        const float* row = in + ci * PITCH;
        u64 vd[4][4];
        #pragma unroll
        for (int r = 0; r < 4; r++) {
            if (r < nr) {
                const int j = (jb + 4 * r) * 32 + lane;
                vd[r][0] = dup2f(row[j - 3 * D]);
                vd[r][1] = dup2f(row[j - 2 * D]);
                vd[r][2] = dup2f(row[j - 1 * D]);
                vd[r][3] = dup2f(row[j]);
            }
        }
        const unsigned wb =
            (unsigned)__cvta_generic_to_shared(wp + ci * 32 + cg * 16);
        #pragma unroll
        for (int p = 0; p < 4; p++) {
            u64 wa = lds64(wb + p * 32 + 0);
            u64 wbv= lds64(wb + p * 32 + 8);
            u64 wc = lds64(wb + p * 32 + 16);
            u64 wd = lds64(wb + p * 32 + 24);
            #pragma unroll
            for (int r = 0; r < 4; r++) {
                if (r < nr) {
                    fma2(acc[p][r], wa, vd[r][0]);
                    fma2(acc[p][r], wbv, vd[r][1]);
                    fma2(acc[p][r], wc, vd[r][2]);
                    fma2(acc[p][r], wd, vd[r][3]);
                }
            }
        }
    }

    #pragma unroll
    for (int p = 0; p < 4; p++) {
        const int co0 = cg * 8 + 2 * p;
        #pragma unroll
        for (int r = 0; r < 4; r++) {
            if (r < nr) {
                const int j = (jb + 4 * r) * 32 + lane;
                if (j >= S) {
                    float a0, a1; unpk(acc[p][r], a0, a1);
                    bool z = (gt0 + j) < 0;
                    out[co0 * PITCH + j]       = z ? 0.f : fmaxf(a0, 0.f);
                    out[(co0 + 1) * PITCH + j] = z ? 0.f : fmaxf(a1, 0.f);
                }
            }
        }
    }
}

__global__ void __launch_bounds__(NTHREADS, 3)
navar_main_kernel(const float* __restrict__ x,
                  const float* __restrict__ w_in, const float* __restrict__ b_in,
                  const float* __restrict__ w_h,  const float* __restrict__ b_h,
                  const float* __restrict__ w_out,const float* __restrict__ b_out,
                  float* __restrict__ out_contrib)
{
    extern __shared__ __align__(16) char smraw[];
    Smem& s = *reinterpret_cast<Smem*>(smraw);
    float* bufA = s.bufs + GUARD;
    float* bufB = bufA + HID * PITCH;
    float* xs   = s.xsb + 4;

    const int tile = blockIdx.x;
    const int g    = blockIdx.y;
    const int b    = blockIdx.z;
    const int t0   = tile * TT;
    const int gt0  = t0 - HALO;
    const int tid  = threadIdx.x;
    const int lane = tid & 31;
    const int wid  = tid >> 5;

    // ---- stage x tile + all params (all 3 hidden layers prestaged) ----
    const float* xg = x + ((size_t)b * GROUPS + g) * T;
    for (int j = tid; j < PITCH; j += NTHREADS) {
        int gt = gt0 + j;
        xs[j] = (gt >= 0 && gt < T) ? xg[gt] : 0.f;
    }
    if (tid < HID * KS) s.w_in[tid] = w_in[g * HID * KS + tid];
    if (tid < HID)      s.b_in[tid] = b_in[g * HID + tid];
    for (int i = tid; i < 3 * HID; i += NTHREADS) {
        int L = i >> 4, co = i & 15;
        s.b_h[i] = b_h[L * GROUPS * HID + g * HID + co];
    }
    for (int i = tid; i < HID * 6 * 2; i += NTHREADS) {
        int half = i & 1, dp = (i >> 1) % 6, ci = (i >> 1) / 6;
        ((float*)s.woutp)[i] = w_out[((size_t)g * NV + 2 * dp + half) * HID + ci];
    }
    if (tid < 12) {
        int half = tid & 1, dp = tid >> 1;
        ((float*)s.boutp)[tid] = b_out[g * NV + 2 * dp + half];
    }
    // hidden weights, co-paired: whp[L][(ci*8+pg)*4+k] = (w[2pg][ci][k], w[2pg+1][ci][k])
    #pragma unroll 1
    for (int L = 0; L < 3; L++) {
        const float* wsrc = w_h + ((size_t)L * GROUPS * HID + (size_t)g * HID) * (HID * KS);
        float* wdst = (float*)s.whp[L];
        #pragma unroll
        for (int r = 0; r < 4; r++) {
            int i = tid + r * NTHREADS;       // 0..1023
            int half = i & 1, k = (i >> 1) & 3, pg = (i >> 3) & 7, ci = i >> 6;
            wdst[i] = wsrc[((2 * pg + half) * HID + ci) * KS + k];
        }
    }
    __syncthreads();

    // ---- input conv 1 -> HID (thread = timestep j) -> bufA ----
    for (int j = tid; j < LL; j += NTHREADS) {
        float xv0 = xs[j - 3], xv1 = xs[j - 2], xv2 = xs[j - 1], xv3 = xs[j];
        const bool neg = (gt0 + j) < 0;
        #pragma unroll
        for (int co = 0; co < HID; co++) {
            float4 w = *(const float4*)(s.w_in + co * 4);
            float a = s.b_in[co];
            a = fmaf(w.x, xv0, a); a = fmaf(w.y, xv1, a);
            a = fmaf(w.z, xv2, a); a = fmaf(w.w, xv3, a);
            bufA[co * PITCH + j] = neg ? 0.f : fmaxf(a, 0.f);
        }
    }
    __syncthreads();

    hidden_cp4<1,  8>(bufA, bufB, s.whp[0], s.b_h,           gt0, lane, wid);
    __syncthreads();
    hidden_cp4<2, 16>(bufB, bufA, s.whp[1], s.b_h + HID,     gt0, lane, wid);
    __syncthreads();
    hidden_cp4<4, 28>(bufA, bufB, s.whp[2], s.b_h + 2 * HID, gt0, lane, wid);
    __syncthreads();

    // ---- 1x1 output conv: thread = TWO consecutive timesteps, 12 dst as
    // 6 packed pairs per timestep; contributions stored as STG.64 t-pairs.
    {
        const int dd  = g / (NS * NV);
        const int rem = g % (NS * NV);
        const int ss  = rem / NV;
        const int src = rem % NV;
        const size_t cbase = ((size_t)((b * ND + dd) * NS + ss) * NV * NV + src) * T;

        for (int trel = tid * 2; trel < TT; trel += 2 * NTHREADS) {
            const int gt = t0 + trel;
            if (gt >= T) break;
            const int jc = HALO + trel;

            u64 a6[6], c6[6];
            #pragma unroll
            for (int dp = 0; dp < 6; dp++) { a6[dp] = s.boutp[dp]; c6[dp] = a6[dp]; }

            #pragma unroll
            for (int ci = 0; ci < HID; ci++) {
                const float* hrow = bufB + ci * PITCH + jc;
                u64 h0 = dup2f(hrow[0]);
                u64 h1 = dup2f(hrow[1]);
                const ulonglong2* w2 = (const ulonglong2*)(s.woutp + ci * 6);
                ulonglong2 wA = w2[0], wB = w2[1], wC = w2[2];
                fma2(a6[0], wA.x, h0); fma2(c6[0], wA.x, h1);
                fma2(a6[1], wA.y, h0); fma2(c6[1], wA.y, h1);
                fma2(a6[2], wB.x, h0); fma2(c6[2], wB.x, h1);
                fma2(a6[3], wB.y, h0); fma2(c6[3], wB.y, h1);
                fma2(a6[4], wC.x, h0); fma2(c6[4], wC.x, h1);
                fma2(a6[5], wC.y, h0); fma2(c6[5], wC.y, h1);
            }
            const bool both = (gt + 1) < T;
            #pragma unroll
            for (int dp = 0; dp < 6; dp++) {
                float lo0, hi0, lo1, hi1;
                unpk(a6[dp], lo0, hi0);
                unpk(c6[dp], lo1, hi1);
                float* p0 = out_contrib + cbase + (size_t)(2 * dp)     * NV * T + gt;
                float* p1 = out_contrib + cbase + (size_t)(2 * dp + 1) * NV * T + gt;
                if (both) {
                    *(float2*)p0 = make_float2(lo0, lo1);
                    *(float2*)p1 = make_float2(hi0, hi1);
                } else {
                    *p0 = lo0;
                    *p1 = hi0;
                }
            }
        }
    }
}

// prediction[b,dd,ss,v,t] = sum_src contrib[b,dd,ss,v,src,t] + biases[dd,ss,v]
__global__ void __launch_bounds__(256)
navar_pred_kernel(const float4* __restrict__ contrib4,
                  const float* __restrict__ biases,
                  float4* __restrict__ pred4)
{
    int idx = blockIdx.x * blockDim.x + threadIdx.x;
    if (idx >= PRED_ELEMS / 4) return;
    int t4 = idx & (T / 4 - 1);
    int r  = idx >> 9;                 // T/4 = 512
    float bsc = biases[r % (ND * NS * NV)];
    const float4* cp = contrib4 + (size_t)r * NV * (T / 4) + t4;
    float4 acc = make_float4(bsc, bsc, bsc, bsc);
    #pragma unroll
    for (int sI = 0; sI < NV; sI++) {
        float4 v = cp[(size_t)sI * (T / 4)];
        acc.x += v.x; acc.y += v.y; acc.z += v.z; acc.w += v.w;
    }
    pred4[idx] = acc;
}

extern "C" void kernel_launch(void* const* d_in, const int* in_sizes, int n_in,
                              void* d_out, int out_size)
{
    const float* x      = (const float*)d_in[0];
    const float* w_in   = (const float*)d_in[1];
    const float* b_in   = (const float*)d_in[2];
    const float* w_h    = (const float*)d_in[3];
    const float* b_h    = (const float*)d_in[4];
    const float* w_out  = (const float*)d_in[5];
    const float* b_out  = (const float*)d_in[6];
    const float* biases = (const float*)d_in[7];

    float* out     = (float*)d_out;
    float* pred    = out;                     // (B,ND,NS,NV,T)
    float* contrib = out + PRED_ELEMS;        // (B,ND,NS,NV,NV,T)

    const int smem_bytes = (int)sizeof(Smem);
    cudaFuncSetAttribute(navar_main_kernel,
                         cudaFuncAttributeMaxDynamicSharedMemorySize, smem_bytes);

    dim3 grid(NTILES, GROUPS, BATCH);
    navar_main_kernel<<<grid, NTHREADS, smem_bytes>>>(
        x, w_in, b_in, w_h, b_h, w_out, b_out, contrib);
    navar_pred_kernel<<<(PRED_ELEMS / 4 + 255) / 256, 256>>>(
        (const float4*)contrib, biases, (float4*)pred);
}

// round 17
// speedup vs baseline: 1.1117x; 1.1102x over previous
#include <cuda_runtime.h>

// ---------------- NAVAR dims ----------------
#define ND      2
#define NS      4
#define NV      12
#define HID     16
#define GROUPS  96
#define KS      4
#define T       2048
#define BATCH   8

// ---------------- tiling ----------------
#define TT      740              // output timesteps per tile (even)
#define HALO    28               // 3 + 3*(1+2+4)
#define LL      (TT + HALO)      // 768 local positions = 24 * 32
#define NJ      24               // j-vectors of 32
#define PITCH   768              // row pitch (floats); 3072 B rows
#define NTHREADS 256
#define NTILES  3                // 3*740 = 2220 >= 2048
#define PRED_ELEMS (BATCH*ND*NS*NV*T)        // 1,572,864
#define GUARD   16               // floats of scratch before bufA (negative-j reads)

typedef unsigned long long u64;

// ---- packed f32x2 helpers (Blackwell) ----
__device__ __forceinline__ u64 pk2(float a, float b) {
    u64 r; asm("mov.b64 %0, {%1, %2};" : "=l"(r) : "f"(a), "f"(b)); return r;
}
__device__ __forceinline__ u64 dup2f(float a) {
    u64 r; asm("mov.b64 %0, {%1, %1};" : "=l"(r) : "f"(a)); return r;
}
__device__ __forceinline__ void fma2(u64 &d, u64 a, u64 b) {
    asm("fma.rn.f32x2 %0, %1, %2, %0;" : "+l"(d) : "l"(a), "l"(b));
}
__device__ __forceinline__ void unpk(u64 v, float &lo, float &hi) {
    asm("mov.b64 {%0, %1}, %2;" : "=f"(lo), "=f"(hi) : "l"(v));
}

struct __align__(16) Smem {
    float bufs[GUARD + 2 * HID * PITCH]; // bufA, bufB back-to-back   98,368 B
    float xsb[4 + PITCH];                //                             3,088 B
    u64   whp[3][HID * 8 * KS];          // all 3 layers co-paired     12,288 B
    u64   woutp[HID * 6];                //                               768 B
    u64   boutp[6];                      //                                48 B
    float w_in[HID * KS];                //                               256 B
    float b_in[HID];                     //                                64 B
    float b_h[3 * HID];                  //                               192 B
};  // 115,072 B dynamic; x2 CTAs = 224.8 KB/SM

// ---- hidden conv HID->HID dilation D: warp = ALL 16 co x 3 jvec ----
// warp q = wid (0..7), jvecs {q, q+8, q+16} (NJ=24: perfectly balanced).
// Per ci: 12 data LDS.32 (shared across all 16 co) + 16 broadcast LDS.128
// weights streamed through the p-loop; 96 FFMA2.
template<int D, int S>
__device__ __forceinline__ void hidden_cp16(
    const float* __restrict__ in, float* __restrict__ out,
    const u64* __restrict__ wp, const float* __restrict__ bl,
    int gt0, int lane, int wid)
{
    const int q = wid;
    int jv[3];
    #pragma unroll
    for (int r = 0; r < 3; r++) jv[r] = (q + 8 * r) * 32 + lane;

    u64 acc[8][3];
    #pragma unroll
    for (int p = 0; p < 8; p++) {
        u64 bp = pk2(bl[2 * p], bl[2 * p + 1]);
        #pragma unroll
        for (int r = 0; r < 3; r++) acc[p][r] = bp;
    }

    #pragma unroll 1
    for (int ci = 0; ci < HID; ci++) {
        const float* row = in + ci * PITCH;
        u64 vd[3][4];
        #pragma unroll
        for (int r = 0; r < 3; r++) {
            vd[r][0] = dup2f(row[jv[r] - 3 * D]);
            vd[r][1] = dup2f(row[jv[r] - 2 * D]);
            vd[r][2] = dup2f(row[jv[r] - 1 * D]);
            vd[r][3] = dup2f(row[jv[r]]);
        }
        const ulonglong2* w2 = (const ulonglong2*)(wp + ci * 32);
        #pragma unroll
        for (int p = 0; p < 8; p++) {
            ulonglong2 wa = w2[2 * p], wb = w2[2 * p + 1];
            #pragma unroll
            for (int r = 0; r < 3; r++) {
                fma2(acc[p][r], wa.x, vd[r][0]);
                fma2(acc[p][r], wa.y, vd[r][1]);
                fma2(acc[p][r], wb.x, vd[r][2]);
                fma2(acc[p][r], wb.y, vd[r][3]);
            }
        }
    }

    #pragma unroll
    for (int p = 0; p < 8; p++) {
        const int co0 = 2 * p;
        #pragma unroll
        for (int r = 0; r < 3; r++) {
            const int j = jv[r];
            if (j >= S) {
                float a0, a1; unpk(acc[p][r], a0, a1);
                bool z = (gt0 + j) < 0;
                out[co0 * PITCH + j]       = z ? 0.f : fmaxf(a0, 0.f);
                out[(co0 + 1) * PITCH + j] = z ? 0.f : fmaxf(a1, 0.f);
            }
        }
    }
}

__global__ void __launch_bounds__(NTHREADS, 2)
navar_main_kernel(const float* __restrict__ x,
                  const float* __restrict__ w_in, const float* __restrict__ b_in,
                  const float* __restrict__ w_h,  const float* __restrict__ b_h,
                  const float* __restrict__ w_out,const float* __restrict__ b_out,
                  float* __restrict__ out_contrib)
{
    extern __shared__ __align__(16) char smraw[];
    Smem& s = *reinterpret_cast<Smem*>(smraw);
    float* bufA = s.bufs + GUARD;
    float* bufB = bufA + HID * PITCH;
    float* xs   = s.xsb + 4;

    const int tile = blockIdx.x;
    const int g    = blockIdx.y;
    const int b    = blockIdx.z;
    const int t0   = tile * TT;
    const int gt0  = t0 - HALO;
    const int tid  = threadIdx.x;
    const int lane = tid & 31;
    const int wid  = tid >> 5;

    // ---- stage x tile + all params (all 3 hidden layers prestaged) ----
    const float* xg = x + ((size_t)b * GROUPS + g) * T;
    for (int j = tid; j < PITCH; j += NTHREADS) {
        int gt = gt0 + j;
        xs[j] = (gt >= 0 && gt < T) ? xg[gt] : 0.f;
    }
    if (tid < HID * KS) s.w_in[tid] = w_in[g * HID * KS + tid];
    if (tid < HID)      s.b_in[tid] = b_in[g * HID + tid];
    for (int i = tid; i < 3 * HID; i += NTHREADS) {
        int L = i >> 4, co = i & 15;
        s.b_h[i] = b_h[L * GROUPS * HID + g * HID + co];
    }
    for (int i = tid; i < HID * 6 * 2; i += NTHREADS) {
        int half = i & 1, dp = (i >> 1) % 6, ci = (i >> 1) / 6;
        ((float*)s.woutp)[i] = w_out[((size_t)g * NV + 2 * dp + half) * HID + ci];
    }
    if (tid < 12) {
        int half = tid & 1, dp = tid >> 1;
        ((float*)s.boutp)[tid] = b_out[g * NV + 2 * dp + half];
    }
    // hidden weights, co-paired: whp[L][(ci*8+pg)*4+k] = (w[2pg][ci][k], w[2pg+1][ci][k])
    #pragma unroll 1
    for (int L = 0; L < 3; L++) {
        const float* wsrc = w_h + ((size_t)L * GROUPS * HID + (size_t)g * HID) * (HID * KS);
        float* wdst = (float*)s.whp[L];
        #pragma unroll
        for (int r = 0; r < 4; r++) {
            int i = tid + r * NTHREADS;       // 0..1023
            int half = i & 1, k = (i >> 1) & 3, pg = (i >> 3) & 7, ci = i >> 6;
            wdst[i] = wsrc[((2 * pg + half) * HID + ci) * KS + k];
        }
    }
    __syncthreads();

    // ---- input conv 1 -> HID (thread = timestep j) -> bufA ----
    for (int j = tid; j < LL; j += NTHREADS) {
        float xv0 = xs[j - 3], xv1 = xs[j - 2], xv2 = xs[j - 1], xv3 = xs[j];
        const bool neg = (gt0 + j) < 0;
        #pragma unroll
        for (int co = 0; co < HID; co++) {
            float4 w = *(const float4*)(s.w_in + co * 4);
            float a = s.b_in[co];
            a = fmaf(w.x, xv0, a); a = fmaf(w.y, xv1, a);
            a = fmaf(w.z, xv2, a); a = fmaf(w.w, xv3, a);
            bufA[co * PITCH + j] = neg ? 0.f : fmaxf(a, 0.f);
        }
    }
    __syncthreads();

    hidden_cp16<1,  8>(bufA, bufB, s.whp[0], s.b_h,           gt0, lane, wid);
    __syncthreads();
    hidden_cp16<2, 16>(bufB, bufA, s.whp[1], s.b_h + HID,     gt0, lane, wid);
    __syncthreads();
    hidden_cp16<4, 28>(bufA, bufB, s.whp[2], s.b_h + 2 * HID, gt0, lane, wid);
    __syncthreads();

    // ---- 1x1 output conv: thread = TWO consecutive timesteps, 12 dst as
    // 6 packed pairs per timestep; contributions stored as STG.64 t-pairs.
    {
        const int dd  = g / (NS * NV);
        const int rem = g % (NS * NV);
        const int ss  = rem / NV;
        const int src = rem % NV;
        const size_t cbase = ((size_t)((b * ND + dd) * NS + ss) * NV * NV + src) * T;

        for (int trel = tid * 2; trel < TT; trel += 2 * NTHREADS) {
            const int gt = t0 + trel;
            if (gt >= T) break;
            const int jc = HALO + trel;

            u64 a6[6], c6[6];
            #pragma unroll
            for (int dp = 0; dp < 6; dp++) { a6[dp] = s.boutp[dp]; c6[dp] = a6[dp]; }

            #pragma unroll
            for (int ci = 0; ci < HID; ci++) {
                const float* hrow = bufB + ci * PITCH + jc;
                u64 h0 = dup2f(hrow[0]);
                u64 h1 = dup2f(hrow[1]);
                const ulonglong2* w2 = (const ulonglong2*)(s.woutp + ci * 6);
                ulonglong2 wA = w2[0], wB = w2[1], wC = w2[2];
                fma2(a6[0], wA.x, h0); fma2(c6[0], wA.x, h1);
                fma2(a6[1], wA.y, h0); fma2(c6[1], wA.y, h1);
                fma2(a6[2], wB.x, h0); fma2(c6[2], wB.x, h1);
                fma2(a6[3], wB.y, h0); fma2(c6[3], wB.y, h1);
                fma2(a6[4], wC.x, h0); fma2(c6[4], wC.x, h1);
                fma2(a6[5], wC.y, h0); fma2(c6[5], wC.y, h1);
            }
            const bool both = (gt + 1) < T;
            #pragma unroll
            for (int dp = 0; dp < 6; dp++) {
                float lo0, hi0, lo1, hi1;
                unpk(a6[dp], lo0, hi0);
                unpk(c6[dp], lo1, hi1);
                float* p0 = out_contrib + cbase + (size_t)(2 * dp)     * NV * T + gt;
                float* p1 = out_contrib + cbase + (size_t)(2 * dp + 1) * NV * T + gt;
                if (both) {
                    *(float2*)p0 = make_float2(lo0, lo1);
                    *(float2*)p1 = make_float2(hi0, hi1);
                } else {
                    *p0 = lo0;
                    *p1 = hi0;
                }
            }
        }
    }
}

// prediction[b,dd,ss,v,t] = sum_src contrib[b,dd,ss,v,src,t] + biases[dd,ss,v]
__global__ void __launch_bounds__(256)
navar_pred_kernel(const float4* __restrict__ contrib4,
                  const float* __restrict__ biases,
                  float4* __restrict__ pred4)
{
    int idx = blockIdx.x * blockDim.x + threadIdx.x;
    if (idx >= PRED_ELEMS / 4) return;
    int t4 = idx & (T / 4 - 1);
    int r  = idx >> 9;                 // T/4 = 512
    float bsc = biases[r % (ND * NS * NV)];
    const float4* cp = contrib4 + (size_t)r * NV * (T / 4) + t4;
    float4 acc = make_float4(bsc, bsc, bsc, bsc);
    #pragma unroll
    for (int sI = 0; sI < NV; sI++) {
        float4 v = cp[(size_t)sI * (T / 4)];
        acc.x += v.x; acc.y += v.y; acc.z += v.z; acc.w += v.w;
    }
    pred4[idx] = acc;
}

extern "C" void kernel_launch(void* const* d_in, const int* in_sizes, int n_in,
                              void* d_out, int out_size)
{
    const float* x      = (const float*)d_in[0];
    const float* w_in   = (const float*)d_in[1];
    const float* b_in   = (const float*)d_in[2];
    const float* w_h    = (const float*)d_in[3];
    const float* b_h    = (const float*)d_in[4];
    const float* w_out  = (const float*)d_in[5];
    const float* b_out  = (const float*)d_in[6];
    const float* biases = (const float*)d_in[7];

    float* out     = (float*)d_out;
    float* pred    = out;                     // (B,ND,NS,NV,T)
    float* contrib = out + PRED_ELEMS;        // (B,ND,NS,NV,NV,T)

    const int smem_bytes = (int)sizeof(Smem);
    cudaFuncSetAttribute(navar_main_kernel,
                         cudaFuncAttributeMaxDynamicSharedMemorySize, smem_bytes);

    dim3 grid(NTILES, GROUPS, BATCH);
    navar_main_kernel<<<grid, NTHREADS, smem_bytes>>>(
        x, w_in, b_in, w_h, b_h, w_out, b_out, contrib);
    navar_pred_kernel<<<(PRED_ELEMS / 4 + 255) / 256, 256>>>(
        (const float4*)contrib, biases, (float4*)pred);
}